// round 16
// baseline (speedup 1.0000x reference)
#include <cuda_runtime.h>
#include <cuda_fp16.h>
#include <cstdint>

#define BATCH 2
#define SEQ   2048
#define DMODEL 1024
#define NHEAD 16
#define DK    64

// fp16 intermediates (allocation-free scratch)
__device__ __half g_q[BATCH*NHEAD*SEQ*DK];
__device__ __half g_k[BATCH*NHEAD*SEQ*DK];
__device__ __half g_v[BATCH*NHEAD*SEQ*DK];
__device__ __half g_attn[BATCH*SEQ*DMODEL];
// fp16 pre-converted weights
__device__ __half g_hwq[DMODEL*DMODEL];
__device__ __half g_hwk[DMODEL*DMODEL];
__device__ __half g_hwv[DMODEL*DMODEL];
__device__ __half g_hwo[DMODEL*DMODEL];

// ---------- helpers ----------
__device__ __forceinline__ unsigned h2(float x, float y) {
    __half2 h = __floats2half2_rn(x, y);
    return *reinterpret_cast<unsigned*>(&h);
}
__device__ __forceinline__ void mma_f16(float c[4],
    unsigned a0, unsigned a1, unsigned a2, unsigned a3,
    unsigned b0, unsigned b1) {
    asm volatile(
        "mma.sync.aligned.m16n8k16.row.col.f32.f16.f16.f32 "
        "{%0,%1,%2,%3},{%4,%5,%6,%7},{%8,%9},{%0,%1,%2,%3};"
        : "+f"(c[0]), "+f"(c[1]), "+f"(c[2]), "+f"(c[3])
        : "r"(a0), "r"(a1), "r"(a2), "r"(a3), "r"(b0), "r"(b1));
}
#define LDSM_X4(r0, r1, r2, r3, addr) \
    asm volatile("ldmatrix.sync.aligned.m8n8.x4.shared.b16 {%0,%1,%2,%3}, [%4];" \
        : "=r"(r0), "=r"(r1), "=r"(r2), "=r"(r3) : "r"(addr))
#define LDSM_X4T(r0, r1, r2, r3, addr) \
    asm volatile("ldmatrix.sync.aligned.m8n8.x4.trans.shared.b16 {%0,%1,%2,%3}, [%4];" \
        : "=r"(r0), "=r"(r1), "=r"(r2), "=r"(r3) : "r"(addr))

// ---------- weight fp32 -> fp16 (one-shot, ~4us) ----------
__global__ __launch_bounds__(256) void cvt_w(
    const float* __restrict__ wq, const float* __restrict__ wk,
    const float* __restrict__ wv, const float* __restrict__ wo)
{
    const float* src; __half* dst;
    switch (blockIdx.y) {
        case 0: src = wq; dst = g_hwq; break;
        case 1: src = wk; dst = g_hwk; break;
        case 2: src = wv; dst = g_hwv; break;
        default: src = wo; dst = g_hwo; break;
    }
    int i = (blockIdx.x * 256 + threadIdx.x) * 8;   // grid.x=512 covers 1M exactly
    float4 v0 = *(const float4*)(src + i);
    float4 v1 = *(const float4*)(src + i + 4);
    uint4 o;
    o.x = h2(v0.x, v0.y); o.y = h2(v0.z, v0.w);
    o.z = h2(v1.x, v1.y); o.w = h2(v1.z, v1.w);
    *(uint4*)(dst + i) = o;
}

// ---------- projection GEMM: C = A @ W^T + bias ----------
// 128x128 CTA tile, K-chunk 32, double-buffered SWIZZLED fp16 smem.
// a_half=0: A fp32 (QKV inputs); a_half=1: A fp16 (g_attn).
// qkv=1: z selects {q,k,v}, fp16 head-split out; qkv=0: fp32 flat out.
#define PAH (128 * 32)                  // halves per tile
#define PSTAGEH (2 * PAH)               // A + W per stage
#define PROJ_SMEM_BYTES (2 * PSTAGEH * 2)   // 32768

__global__ __launch_bounds__(256, 2) void proj_gemm(
    const void* __restrict__ A0, const __half* __restrict__ W0,
    const float* __restrict__ B0, void* __restrict__ C0,
    const void* __restrict__ A1, const __half* __restrict__ W1,
    const float* __restrict__ B1, void* __restrict__ C1,
    const void* __restrict__ A2, const __half* __restrict__ W2,
    const float* __restrict__ B2, void* __restrict__ C2,
    int qkv, int a_half)
{
    extern __shared__ __half smh[];
    const void* Av = A0; const __half* W = W0; const float* bias = B0;
    void* C = C0;
    if (qkv) {
        if (blockIdx.z == 1) { Av = A1; W = W1; bias = B1; C = C1; }
        else if (blockIdx.z == 2) { Av = A2; W = W2; bias = B2; C = C2; }
    }
    const int tid = threadIdx.x, lane = tid & 31, w = tid >> 5;
    const int g = lane >> 2, t = lane & 3;
    const int wr = w >> 1, wc = w & 1;
    const int mbase = blockIdx.y * 128, nbase = blockIdx.x * 128;

    // loader mapping: 4 threads/row, uint4 (8 halves) each; 2 passes (+64 rows)
    const int srow = tid >> 2, sgv = tid & 3;
    const int sg2 = sgv ^ ((srow >> 1) & 3);   // swizzled group (row>>1 same both passes)

    float c[2][8][4];
#pragma unroll
    for (int mt = 0; mt < 2; mt++)
#pragma unroll
        for (int nt = 0; nt < 8; nt++)
#pragma unroll
            for (int i = 0; i < 4; i++) c[mt][nt][i] = 0.f;

    float4 ra[2][2]; uint4 ah[2], rw[2];
    auto ldg = [&](int kt) {
#pragma unroll
        for (int p = 0; p < 2; p++) {
            int row = srow + p * 64;
            if (a_half) {
                ah[p] = *(const uint4*)((const __half*)Av + (size_t)(mbase + row) * 1024 + kt * 32 + sgv * 8);
            } else {
                const float* Ap = (const float*)Av + (size_t)(mbase + row) * 1024 + kt * 32 + sgv * 8;
                ra[p][0] = *(const float4*)(Ap);
                ra[p][1] = *(const float4*)(Ap + 4);
            }
            rw[p] = *(const uint4*)(W + (size_t)(nbase + row) * 1024 + kt * 32 + sgv * 8);
        }
    };
    auto sts = [&](int s) {
        __half* As = smh + s * PSTAGEH;
        __half* Ws = As + PAH;
#pragma unroll
        for (int p = 0; p < 2; p++) {
            int row = srow + p * 64;
            uint4 av;
            if (a_half) av = ah[p];
            else {
                av.x = h2(ra[p][0].x, ra[p][0].y); av.y = h2(ra[p][0].z, ra[p][0].w);
                av.z = h2(ra[p][1].x, ra[p][1].y); av.w = h2(ra[p][1].z, ra[p][1].w);
            }
            *(uint4*)(As + row * 32 + sg2 * 8) = av;
            *(uint4*)(Ws + row * 32 + sg2 * 8) = rw[p];
        }
    };

    ldg(0); sts(0); ldg(1);
    __syncthreads();

    const int wro = wr * 32, wco = wc * 64;
    // ldmatrix lane geometry
    const int hiA = (lane >> 4) & 1;
    const int rxA = ((lane & 15) >> 1) & 3;
    const int rB  = (lane & 7) + ((lane & 16) >> 1);
    const int hiB = (lane >> 3) & 1;
    const int rxB = (rB >> 1) & 3;
    const uint32_t smb = (uint32_t)__cvta_generic_to_shared(smh);
    const uint32_t aLane = smb + (uint32_t)((wro + (lane & 15)) * 32 * 2);
    const uint32_t bLane = smb + (uint32_t)((PAH + (wco + rB) * 32) * 2);

    for (int kt = 0; kt < 32; kt++) {
        if (kt + 1 < 32) sts((kt + 1) & 1);
        if (kt + 2 < 32) ldg(kt + 2);
        const uint32_t stB = (uint32_t)((kt & 1) * PSTAGEH * 2);
#pragma unroll
        for (int kk = 0; kk < 2; kk++) {
            const uint32_t sgA = (uint32_t)(((kk * 2 + hiA) ^ rxA) * 16);
            const uint32_t sgB = (uint32_t)(((kk * 2 + hiB) ^ rxB) * 16);
            unsigned a[2][4], b[8][2];
#pragma unroll
            for (int mt = 0; mt < 2; mt++)
                LDSM_X4(a[mt][0], a[mt][1], a[mt][2], a[mt][3],
                        aLane + stB + (uint32_t)(mt * 1024) + sgA);
#pragma unroll
            for (int j = 0; j < 4; j++)
                LDSM_X4(b[2 * j][0], b[2 * j][1], b[2 * j + 1][0], b[2 * j + 1][1],
                        bLane + stB + (uint32_t)(j * 1024) + sgB);
#pragma unroll
            for (int mt = 0; mt < 2; mt++)
#pragma unroll
                for (int nt = 0; nt < 8; nt++)
                    mma_f16(c[mt][nt], a[mt][0], a[mt][1], a[mt][2], a[mt][3],
                            b[nt][0], b[nt][1]);
        }
        __syncthreads();
    }
    // epilogue
#pragma unroll
    for (int mt = 0; mt < 2; mt++)
#pragma unroll
        for (int nt = 0; nt < 8; nt++) {
            int rg0 = mbase + wro + mt * 16 + g;
            int ng = nbase + wco + nt * 8 + 2 * t;   // even
            float b0 = __ldg(bias + ng), b1 = __ldg(bias + ng + 1);
#pragma unroll
            for (int half_ = 0; half_ < 2; half_++) {
                int mg = rg0 + half_ * 8;
                float v0 = c[mt][nt][2 * half_]     + b0;
                float v1 = c[mt][nt][2 * half_ + 1] + b1;
                if (qkv) {
                    int b_ = mg >> 11, s = mg & 2047, h = ng >> 6, d = ng & 63;
                    __half* op = (__half*)C + ((size_t)((b_ * NHEAD + h) * SEQ + s)) * DK + d;
                    *(__half2*)op = __floats2half2_rn(v0, v1);
                } else {
                    float* op = (float*)C + (size_t)mg * DMODEL + ng;
                    op[0] = v0; op[1] = v1;
                }
            }
        }
}

// ---------- flash attention (fp16 in/out, swizzled smem) ----------
#define AQH (128 * 64)                 // 8192 halves
#define AKH (64 * 64)                  // 4096 halves
#define ASTAGEH (2 * AKH)              // 8192 halves per stage (K+V)
#define ATTN_SMEM_BYTES ((AQH + 2 * ASTAGEH) * 2)   // 49152

__global__ __launch_bounds__(256, 2) void attn_kernel()
{
    extern __shared__ __half smh[];
    const int qt = 15 - blockIdx.x;
    const int bh = blockIdx.y;
    const int qbase = qt * 128;
    const __half* qp = g_q + (size_t)bh * SEQ * DK;
    const __half* kp = g_k + (size_t)bh * SEQ * DK;
    const __half* vp = g_v + (size_t)bh * SEQ * DK;

    const int tid = threadIdx.x, lane = tid & 31, w = tid >> 5;
    const int g = lane >> 2, t = lane & 3;
    const int nkt = 2 * qt + 2;

    // loader mapping: 8 threads/row, uint4 each; swizzle group
    const int srow = tid >> 3, sgv = tid & 7;
    const int sg2 = sgv ^ (srow & 7);          // (row+32k)&7 == row&7

    // ---- load Q tile (fp16 copy, swizzled) ----
#pragma unroll
    for (int i = 0; i < 4; i++) {
        int row = srow + i * 32;
        uint4 v = *(const uint4*)(qp + (size_t)(qbase + row) * DK + sgv * 8);
        *(uint4*)(smh + row * 64 + sg2 * 8) = v;
    }

    uint4 kr[2], vr[2];
    auto ldg_kv = [&](int kt) {
        const __half* kpn = kp + (size_t)(kt * 64) * DK;
        const __half* vpn = vp + (size_t)(kt * 64) * DK;
#pragma unroll
        for (int i = 0; i < 2; i++) {
            int row = srow + i * 32;
            kr[i] = *(const uint4*)(kpn + (size_t)row * DK + sgv * 8);
            vr[i] = *(const uint4*)(vpn + (size_t)row * DK + sgv * 8);
        }
    };
    auto sts_kv = [&](int s) {
        __half* Ks = smh + AQH + s * ASTAGEH;
        __half* Vs = Ks + AKH;
#pragma unroll
        for (int i = 0; i < 2; i++) {
            int row = srow + i * 32;
            *(uint4*)(Ks + row * 64 + sg2 * 8) = kr[i];
            *(uint4*)(Vs + row * 64 + sg2 * 8) = vr[i];
        }
    };

    float m0 = -1e30f, m1 = -1e30f, l0 = 0.f, l1 = 0.f;
    float o[8][4];
#pragma unroll
    for (int nt = 0; nt < 8; nt++)
#pragma unroll
        for (int i = 0; i < 4; i++) o[nt][i] = 0.f;

    ldg_kv(0); sts_kv(0);
    ldg_kv(1);
    __syncthreads();

    // ldmatrix lane geometry
    const int rx = lane & 7;
    const int hiA = (lane >> 4) & 1;
    const int hiB = (lane >> 3) & 1;
    const uint32_t smb = (uint32_t)__cvta_generic_to_shared(smh);
    const uint32_t qLane = smb + (uint32_t)((w * 16 + (lane & 15)) * 128);
    const uint32_t kRowB = (uint32_t)(((lane & 7) + ((lane & 16) >> 1)) * 128);
    const uint32_t vRowB = (uint32_t)((lane & 15) * 128);

    for (int kt = 0; kt < nkt; kt++) {
        if (kt + 1 < nkt) sts_kv((kt + 1) & 1);
        if (kt + 2 < nkt) ldg_kv(kt + 2);
        const uint32_t stB = (uint32_t)((AQH + (kt & 1) * ASTAGEH) * 2);
        const int kb = kt * 64;

        // ---- S = Q @ K^T ----
        float s[8][4];
#pragma unroll
        for (int nt = 0; nt < 8; nt++)
#pragma unroll
            for (int i = 0; i < 4; i++) s[nt][i] = 0.f;
#pragma unroll
        for (int kk = 0; kk < 4; kk++) {
            unsigned a0, a1, a2, a3;
            LDSM_X4(a0, a1, a2, a3,
                    qLane + (uint32_t)(((kk * 2 + hiA) ^ rx) * 16));
            const uint32_t sgB = (uint32_t)(((kk * 2 + hiB) ^ rx) * 16);
            unsigned b[8][2];
#pragma unroll
            for (int j = 0; j < 4; j++)
                LDSM_X4(b[2 * j][0], b[2 * j][1], b[2 * j + 1][0], b[2 * j + 1][1],
                        smb + stB + kRowB + (uint32_t)(j * 2048) + sgB);
#pragma unroll
            for (int nt = 0; nt < 8; nt++)
                mma_f16(s[nt], a0, a1, a2, a3, b[nt][0], b[nt][1]);
        }

        // ---- scale + causal mask ----
        const bool masked = (kb + 64 > qbase);
        const int r0 = qbase + w * 16 + g, r1 = r0 + 8;
#pragma unroll
        for (int nt = 0; nt < 8; nt++) {
            int cg = kb + nt * 8 + 2 * t;
            s[nt][0] *= 0.125f; s[nt][1] *= 0.125f;
            s[nt][2] *= 0.125f; s[nt][3] *= 0.125f;
            if (masked) {
                if (cg     > r0) s[nt][0] = -1e9f;
                if (cg + 1 > r0) s[nt][1] = -1e9f;
                if (cg     > r1) s[nt][2] = -1e9f;
                if (cg + 1 > r1) s[nt][3] = -1e9f;
            }
        }

        // ---- warp-local online softmax ----
        float mc0 = -1e30f, mc1 = -1e30f;
#pragma unroll
        for (int nt = 0; nt < 8; nt++) {
            mc0 = fmaxf(mc0, fmaxf(s[nt][0], s[nt][1]));
            mc1 = fmaxf(mc1, fmaxf(s[nt][2], s[nt][3]));
        }
        mc0 = fmaxf(mc0, __shfl_xor_sync(0xffffffffu, mc0, 1));
        mc0 = fmaxf(mc0, __shfl_xor_sync(0xffffffffu, mc0, 2));
        mc1 = fmaxf(mc1, __shfl_xor_sync(0xffffffffu, mc1, 1));
        mc1 = fmaxf(mc1, __shfl_xor_sync(0xffffffffu, mc1, 2));
        float mn0 = fmaxf(m0, mc0), mn1 = fmaxf(m1, mc1);
        float al0 = __expf(m0 - mn0), al1 = __expf(m1 - mn1);
        m0 = mn0; m1 = mn1;
        l0 *= al0; l1 *= al1;
        float rs0 = 0.f, rs1 = 0.f;
#pragma unroll
        for (int nt = 0; nt < 8; nt++) {
            float p0 = __expf(s[nt][0] - mn0);
            float p1 = __expf(s[nt][1] - mn0);
            float p2 = __expf(s[nt][2] - mn1);
            float p3 = __expf(s[nt][3] - mn1);
            rs0 += p0 + p1; rs1 += p2 + p3;
            s[nt][0] = p0; s[nt][1] = p1;
            s[nt][2] = p2; s[nt][3] = p3;
            o[nt][0] *= al0; o[nt][1] *= al0;
            o[nt][2] *= al1; o[nt][3] *= al1;
        }
        rs0 += __shfl_xor_sync(0xffffffffu, rs0, 1);
        rs0 += __shfl_xor_sync(0xffffffffu, rs0, 2);
        rs1 += __shfl_xor_sync(0xffffffffu, rs1, 1);
        rs1 += __shfl_xor_sync(0xffffffffu, rs1, 2);
        l0 += rs0; l1 += rs1;

        // ---- O += P @ V (packed P frags, swizzled trans-LDSM V) ----
#pragma unroll
        for (int kk = 0; kk < 4; kk++) {
            unsigned a0 = h2(s[2 * kk][0],     s[2 * kk][1]);
            unsigned a1 = h2(s[2 * kk][2],     s[2 * kk][3]);
            unsigned a2 = h2(s[2 * kk + 1][0], s[2 * kk + 1][1]);
            unsigned a3 = h2(s[2 * kk + 1][2], s[2 * kk + 1][3]);
            const uint32_t vkb = smb + stB + (uint32_t)(AKH * 2) + vRowB
                               + (uint32_t)(kk * 2048);
#pragma unroll
            for (int ntp = 0; ntp < 4; ntp++) {
                unsigned r0_, r1_, r2_, r3_;
                LDSM_X4T(r0_, r1_, r2_, r3_,
                         vkb + (uint32_t)(((ntp * 2 + hiA) ^ rx) * 16));
                mma_f16(o[2 * ntp],     a0, a1, a2, a3, r0_, r1_);
                mma_f16(o[2 * ntp + 1], a0, a1, a2, a3, r2_, r3_);
            }
        }
        __syncthreads();
    }

    // ---- epilogue: O/l, merge heads -> g_attn fp16 [B,S,DMODEL] ----
    const int b_ = bh >> 4, h = bh & 15;
    const float il0 = 1.f / l0, il1 = 1.f / l1;
    __half* outp = g_attn + ((size_t)b_ * SEQ + qbase) * DMODEL + h * DK;
    const int rl0 = w * 16 + g;
#pragma unroll
    for (int nt = 0; nt < 8; nt++) {
        int dl = nt * 8 + 2 * t;
        *(__half2*)(outp + (size_t)rl0 * DMODEL + dl) =
            __floats2half2_rn(o[nt][0] * il0, o[nt][1] * il0);
        *(__half2*)(outp + (size_t)(rl0 + 8) * DMODEL + dl) =
            __floats2half2_rn(o[nt][2] * il1, o[nt][3] * il1);
    }
}

// ---------- launch ----------
extern "C" void kernel_launch(void* const* d_in, const int* in_sizes, int n_in,
                              void* d_out, int out_size)
{
    const float* q  = (const float*)d_in[0];
    const float* k  = (const float*)d_in[1];
    const float* v  = (const float*)d_in[2];
    const float* wq = (const float*)d_in[4];
    const float* bq = (const float*)d_in[5];
    const float* wk = (const float*)d_in[6];
    const float* bk = (const float*)d_in[7];
    const float* wv = (const float*)d_in[8];
    const float* bv = (const float*)d_in[9];
    const float* wo = (const float*)d_in[10];
    const float* bo = (const float*)d_in[11];

    __half *pq, *pk, *pv, *pa, *phwq, *phwk, *phwv, *phwo;
    cudaGetSymbolAddress((void**)&pq,   g_q);
    cudaGetSymbolAddress((void**)&pk,   g_k);
    cudaGetSymbolAddress((void**)&pv,   g_v);
    cudaGetSymbolAddress((void**)&pa,   g_attn);
    cudaGetSymbolAddress((void**)&phwq, g_hwq);
    cudaGetSymbolAddress((void**)&phwk, g_hwk);
    cudaGetSymbolAddress((void**)&phwv, g_hwv);
    cudaGetSymbolAddress((void**)&phwo, g_hwo);

    cudaFuncSetAttribute(proj_gemm,
                         cudaFuncAttributeMaxDynamicSharedMemorySize,
                         PROJ_SMEM_BYTES);
    cudaFuncSetAttribute(attn_kernel,
                         cudaFuncAttributeMaxDynamicSharedMemorySize,
                         ATTN_SMEM_BYTES);

    cvt_w<<<dim3(512, 4), 256>>>(wq, wk, wv, wo);

    proj_gemm<<<dim3(8, 32, 3), 256, PROJ_SMEM_BYTES>>>(
        q, phwq, bq, pq,
        k, phwk, bk, pk,
        v, phwv, bv, pv, 1, 0);

    attn_kernel<<<dim3(16, 32), 256, ATTN_SMEM_BYTES>>>();

    proj_gemm<<<dim3(8, 32, 1), 256, PROJ_SMEM_BYTES>>>(
        pa, phwo, bo, d_out,
        nullptr, nullptr, nullptr, nullptr,
        nullptr, nullptr, nullptr, nullptr, 0, 1);
}

// round 17
// speedup vs baseline: 1.1182x; 1.1182x over previous
#include <cuda_runtime.h>
#include <cuda_fp16.h>
#include <cstdint>

#define BATCH 2
#define SEQ   2048
#define DMODEL 1024
#define NHEAD 16
#define DK    64

// fp16 intermediates (allocation-free scratch)
__device__ __half g_q[BATCH*NHEAD*SEQ*DK];
__device__ __half g_k[BATCH*NHEAD*SEQ*DK];
__device__ __half g_v[BATCH*NHEAD*SEQ*DK];
__device__ __half g_attn[BATCH*SEQ*DMODEL];
// fp16 pre-converted weights
__device__ __half g_hwq[DMODEL*DMODEL];
__device__ __half g_hwk[DMODEL*DMODEL];
__device__ __half g_hwv[DMODEL*DMODEL];
__device__ __half g_hwo[DMODEL*DMODEL];

// ---------- helpers ----------
__device__ __forceinline__ unsigned h2(float x, float y) {
    __half2 h = __floats2half2_rn(x, y);
    return *reinterpret_cast<unsigned*>(&h);
}
__device__ __forceinline__ void mma_f16(float c[4],
    unsigned a0, unsigned a1, unsigned a2, unsigned a3,
    unsigned b0, unsigned b1) {
    asm volatile(
        "mma.sync.aligned.m16n8k16.row.col.f32.f16.f16.f32 "
        "{%0,%1,%2,%3},{%4,%5,%6,%7},{%8,%9},{%0,%1,%2,%3};"
        : "+f"(c[0]), "+f"(c[1]), "+f"(c[2]), "+f"(c[3])
        : "r"(a0), "r"(a1), "r"(a2), "r"(a3), "r"(b0), "r"(b1));
}
#define LDSM_X4(r0, r1, r2, r3, addr) \
    asm volatile("ldmatrix.sync.aligned.m8n8.x4.shared.b16 {%0,%1,%2,%3}, [%4];" \
        : "=r"(r0), "=r"(r1), "=r"(r2), "=r"(r3) : "r"(addr))
#define LDSM_X4T(r0, r1, r2, r3, addr) \
    asm volatile("ldmatrix.sync.aligned.m8n8.x4.trans.shared.b16 {%0,%1,%2,%3}, [%4];" \
        : "=r"(r0), "=r"(r1), "=r"(r2), "=r"(r3) : "r"(addr))

// ---------- weight fp32 -> fp16 (one-shot) ----------
__global__ __launch_bounds__(256) void cvt_w(
    const float* __restrict__ wq, const float* __restrict__ wk,
    const float* __restrict__ wv, const float* __restrict__ wo)
{
    const float* src; __half* dst;
    switch (blockIdx.y) {
        case 0: src = wq; dst = g_hwq; break;
        case 1: src = wk; dst = g_hwk; break;
        case 2: src = wv; dst = g_hwv; break;
        default: src = wo; dst = g_hwo; break;
    }
    int i = (blockIdx.x * 256 + threadIdx.x) * 8;
    float4 v0 = *(const float4*)(src + i);
    float4 v1 = *(const float4*)(src + i + 4);
    uint4 o;
    o.x = h2(v0.x, v0.y); o.y = h2(v0.z, v0.w);
    o.z = h2(v1.x, v1.y); o.w = h2(v1.z, v1.w);
    *(uint4*)(dst + i) = o;
}

// ---------- projection GEMM: C = A @ W^T + bias ----------
// 128x128 CTA tile, K-chunk 64 (16 barriers), double-buffered swizzled fp16
// smem (64-half rows, 8-group XOR — same layout as attention tiles).
#define PAH (128 * 64)                  // halves per tile (8192)
#define PSTAGEH (2 * PAH)               // A + W per stage
#define PROJ_SMEM_BYTES (2 * PSTAGEH * 2)   // 65536

__global__ __launch_bounds__(256, 2) void proj_gemm(
    const void* __restrict__ A0, const __half* __restrict__ W0,
    const float* __restrict__ B0, void* __restrict__ C0,
    const void* __restrict__ A1, const __half* __restrict__ W1,
    const float* __restrict__ B1, void* __restrict__ C1,
    const void* __restrict__ A2, const __half* __restrict__ W2,
    const float* __restrict__ B2, void* __restrict__ C2,
    int qkv, int a_half)
{
    extern __shared__ __half smh[];
    const void* Av = A0; const __half* W = W0; const float* bias = B0;
    void* C = C0;
    if (qkv) {
        if (blockIdx.z == 1) { Av = A1; W = W1; bias = B1; C = C1; }
        else if (blockIdx.z == 2) { Av = A2; W = W2; bias = B2; C = C2; }
    }
    const int tid = threadIdx.x, lane = tid & 31, w = tid >> 5;
    const int g = lane >> 2, t = lane & 3;
    const int wr = w >> 1, wc = w & 1;
    const int mbase = blockIdx.y * 128, nbase = blockIdx.x * 128;

    // loader: 8 threads/row, uint4 (8 halves); 4 passes of 32 rows
    const int srow = tid >> 3, sgv = tid & 7;
    const int sg2 = sgv ^ (srow & 7);       // (srow+32p)&7 == srow&7

    float c[2][8][4];
#pragma unroll
    for (int mt = 0; mt < 2; mt++)
#pragma unroll
        for (int nt = 0; nt < 8; nt++)
#pragma unroll
            for (int i = 0; i < 4; i++) c[mt][nt][i] = 0.f;

    uint4 ah[4], rw[4];
    auto ldg = [&](int kt) {
#pragma unroll
        for (int p = 0; p < 4; p++) {
            int row = srow + p * 32;
            if (a_half) {
                ah[p] = *(const uint4*)((const __half*)Av + (size_t)(mbase + row) * 1024 + kt * 64 + sgv * 8);
            } else {
                const float* Ap = (const float*)Av + (size_t)(mbase + row) * 1024 + kt * 64 + sgv * 8;
                float4 f0 = *(const float4*)(Ap);
                float4 f1 = *(const float4*)(Ap + 4);
                ah[p].x = h2(f0.x, f0.y); ah[p].y = h2(f0.z, f0.w);
                ah[p].z = h2(f1.x, f1.y); ah[p].w = h2(f1.z, f1.w);
            }
            rw[p] = *(const uint4*)(W + (size_t)(nbase + row) * 1024 + kt * 64 + sgv * 8);
        }
    };
    auto sts = [&](int s) {
        __half* As = smh + s * PSTAGEH;
        __half* Ws = As + PAH;
#pragma unroll
        for (int p = 0; p < 4; p++) {
            int row = srow + p * 32;
            *(uint4*)(As + row * 64 + sg2 * 8) = ah[p];
            *(uint4*)(Ws + row * 64 + sg2 * 8) = rw[p];
        }
    };

    ldg(0); sts(0); ldg(1);
    __syncthreads();

    const int wro = wr * 32, wco = wc * 64;
    // ldmatrix lane geometry (64-half rows; same as attention pattern)
    const int rx = lane & 7;
    const int hiA = (lane >> 4) & 1;
    const int hiB = (lane >> 3) & 1;
    const int rB  = (lane & 7) + ((lane & 16) >> 1);
    const uint32_t smb = (uint32_t)__cvta_generic_to_shared(smh);
    const uint32_t aLane = smb + (uint32_t)((wro + (lane & 15)) * 128);
    const uint32_t bLane = smb + (uint32_t)((PAH + (wco + rB) * 64) * 2);

    for (int kt = 0; kt < 16; kt++) {
        if (kt + 1 < 16) sts((kt + 1) & 1);
        if (kt + 2 < 16) ldg(kt + 2);
        const uint32_t stB = (uint32_t)((kt & 1) * PSTAGEH * 2);
#pragma unroll
        for (int kk = 0; kk < 4; kk++) {
            const uint32_t sgA = (uint32_t)(((kk * 2 + hiA) ^ rx) * 16);
            const uint32_t sgB = (uint32_t)(((kk * 2 + hiB) ^ rx) * 16);
            unsigned a[2][4], b[8][2];
#pragma unroll
            for (int mt = 0; mt < 2; mt++)
                LDSM_X4(a[mt][0], a[mt][1], a[mt][2], a[mt][3],
                        aLane + stB + (uint32_t)(mt * 2048) + sgA);
#pragma unroll
            for (int j = 0; j < 4; j++)
                LDSM_X4(b[2 * j][0], b[2 * j][1], b[2 * j + 1][0], b[2 * j + 1][1],
                        bLane + stB + (uint32_t)(j * 2048) + sgB);
#pragma unroll
            for (int mt = 0; mt < 2; mt++)
#pragma unroll
                for (int nt = 0; nt < 8; nt++)
                    mma_f16(c[mt][nt], a[mt][0], a[mt][1], a[mt][2], a[mt][3],
                            b[nt][0], b[nt][1]);
        }
        __syncthreads();
    }
    // epilogue
#pragma unroll
    for (int mt = 0; mt < 2; mt++)
#pragma unroll
        for (int nt = 0; nt < 8; nt++) {
            int rg0 = mbase + wro + mt * 16 + g;
            int ng = nbase + wco + nt * 8 + 2 * t;
            float b0 = __ldg(bias + ng), b1 = __ldg(bias + ng + 1);
#pragma unroll
            for (int half_ = 0; half_ < 2; half_++) {
                int mg = rg0 + half_ * 8;
                float v0 = c[mt][nt][2 * half_]     + b0;
                float v1 = c[mt][nt][2 * half_ + 1] + b1;
                if (qkv) {
                    int b_ = mg >> 11, s = mg & 2047, h = ng >> 6, d = ng & 63;
                    __half* op = (__half*)C + ((size_t)((b_ * NHEAD + h) * SEQ + s)) * DK + d;
                    *(__half2*)op = __floats2half2_rn(v0, v1);
                } else {
                    float* op = (float*)C + (size_t)mg * DMODEL + ng;
                    op[0] = v0; op[1] = v1;
                }
            }
        }
}

// ---------- flash attention (fp16, swizzled smem, exp2-folded softmax) ----------
#define AQH (128 * 64)
#define AKH (64 * 64)
#define ASTAGEH (2 * AKH)
#define ATTN_SMEM_BYTES ((AQH + 2 * ASTAGEH) * 2)   // 49152
#define CSC 0.1803368801111204f   // 0.125 * log2(e)

__global__ __launch_bounds__(256, 2) void attn_kernel()
{
    extern __shared__ __half smh[];
    const int qt = 15 - blockIdx.x;
    const int bh = blockIdx.y;
    const int qbase = qt * 128;
    const __half* qp = g_q + (size_t)bh * SEQ * DK;
    const __half* kp = g_k + (size_t)bh * SEQ * DK;
    const __half* vp = g_v + (size_t)bh * SEQ * DK;

    const int tid = threadIdx.x, lane = tid & 31, w = tid >> 5;
    const int g = lane >> 2, t = lane & 3;
    const int nkt = 2 * qt + 2;

    const int srow = tid >> 3, sgv = tid & 7;
    const int sg2 = sgv ^ (srow & 7);

    // ---- load Q tile (swizzled) ----
#pragma unroll
    for (int i = 0; i < 4; i++) {
        int row = srow + i * 32;
        uint4 v = *(const uint4*)(qp + (size_t)(qbase + row) * DK + sgv * 8);
        *(uint4*)(smh + row * 64 + sg2 * 8) = v;
    }

    uint4 kr[2], vr[2];
    auto ldg_kv = [&](int kt) {
        const __half* kpn = kp + (size_t)(kt * 64) * DK;
        const __half* vpn = vp + (size_t)(kt * 64) * DK;
#pragma unroll
        for (int i = 0; i < 2; i++) {
            int row = srow + i * 32;
            kr[i] = *(const uint4*)(kpn + (size_t)row * DK + sgv * 8);
            vr[i] = *(const uint4*)(vpn + (size_t)row * DK + sgv * 8);
        }
    };
    auto sts_kv = [&](int s) {
        __half* Ks = smh + AQH + s * ASTAGEH;
        __half* Vs = Ks + AKH;
#pragma unroll
        for (int i = 0; i < 2; i++) {
            int row = srow + i * 32;
            *(uint4*)(Ks + row * 64 + sg2 * 8) = kr[i];
            *(uint4*)(Vs + row * 64 + sg2 * 8) = vr[i];
        }
    };

    float m0 = -1e30f, m1 = -1e30f, l0 = 0.f, l1 = 0.f;
    float o[8][4];
#pragma unroll
    for (int nt = 0; nt < 8; nt++)
#pragma unroll
        for (int i = 0; i < 4; i++) o[nt][i] = 0.f;

    ldg_kv(0); sts_kv(0);
    ldg_kv(1);
    __syncthreads();

    const int rx = lane & 7;
    const int hiA = (lane >> 4) & 1;
    const int hiB = (lane >> 3) & 1;
    const uint32_t smb = (uint32_t)__cvta_generic_to_shared(smh);
    const uint32_t qLane = smb + (uint32_t)((w * 16 + (lane & 15)) * 128);
    const uint32_t kRowB = (uint32_t)(((lane & 7) + ((lane & 16) >> 1)) * 128);
    const uint32_t vRowB = (uint32_t)((lane & 15) * 128);

    for (int kt = 0; kt < nkt; kt++) {
        if (kt + 1 < nkt) sts_kv((kt + 1) & 1);
        if (kt + 2 < nkt) ldg_kv(kt + 2);
        const uint32_t stB = (uint32_t)((AQH + (kt & 1) * ASTAGEH) * 2);
        const int kb = kt * 64;

        // ---- S = Q @ K^T (raw logits; scale folded into exp2) ----
        float s[8][4];
#pragma unroll
        for (int nt = 0; nt < 8; nt++)
#pragma unroll
            for (int i = 0; i < 4; i++) s[nt][i] = 0.f;
#pragma unroll
        for (int kk = 0; kk < 4; kk++) {
            unsigned a0, a1, a2, a3;
            LDSM_X4(a0, a1, a2, a3,
                    qLane + (uint32_t)(((kk * 2 + hiA) ^ rx) * 16));
            const uint32_t sgB = (uint32_t)(((kk * 2 + hiB) ^ rx) * 16);
            unsigned b[8][2];
#pragma unroll
            for (int j = 0; j < 4; j++)
                LDSM_X4(b[2 * j][0], b[2 * j][1], b[2 * j + 1][0], b[2 * j + 1][1],
                        smb + stB + kRowB + (uint32_t)(j * 2048) + sgB);
#pragma unroll
            for (int nt = 0; nt < 8; nt++)
                mma_f16(s[nt], a0, a1, a2, a3, b[nt][0], b[nt][1]);
        }

        // ---- causal mask (raw units) ----
        const bool masked = (kb + 64 > qbase);
        const int r0 = qbase + w * 16 + g, r1 = r0 + 8;
        if (masked) {
#pragma unroll
            for (int nt = 0; nt < 8; nt++) {
                int cg = kb + nt * 8 + 2 * t;
                if (cg     > r0) s[nt][0] = -1e9f;
                if (cg + 1 > r0) s[nt][1] = -1e9f;
                if (cg     > r1) s[nt][2] = -1e9f;
                if (cg + 1 > r1) s[nt][3] = -1e9f;
            }
        }

        // ---- warp-local online softmax (exp2, folded scale) ----
        float mc0 = -1e30f, mc1 = -1e30f;
#pragma unroll
        for (int nt = 0; nt < 8; nt++) {
            mc0 = fmaxf(mc0, fmaxf(s[nt][0], s[nt][1]));
            mc1 = fmaxf(mc1, fmaxf(s[nt][2], s[nt][3]));
        }
        mc0 = fmaxf(mc0, __shfl_xor_sync(0xffffffffu, mc0, 1));
        mc0 = fmaxf(mc0, __shfl_xor_sync(0xffffffffu, mc0, 2));
        mc1 = fmaxf(mc1, __shfl_xor_sync(0xffffffffu, mc1, 1));
        mc1 = fmaxf(mc1, __shfl_xor_sync(0xffffffffu, mc1, 2));
        float mn0 = fmaxf(m0, mc0), mn1 = fmaxf(m1, mc1);
        float al0 = exp2f((m0 - mn0) * CSC), al1 = exp2f((m1 - mn1) * CSC);
        m0 = mn0; m1 = mn1;
        const float mb0 = mn0 * CSC, mb1 = mn1 * CSC;
        l0 *= al0; l1 *= al1;
        float rs0 = 0.f, rs1 = 0.f;
#pragma unroll
        for (int nt = 0; nt < 8; nt++) {
            float p0 = exp2f(fmaf(s[nt][0], CSC, -mb0));
            float p1 = exp2f(fmaf(s[nt][1], CSC, -mb0));
            float p2 = exp2f(fmaf(s[nt][2], CSC, -mb1));
            float p3 = exp2f(fmaf(s[nt][3], CSC, -mb1));
            rs0 += p0 + p1; rs1 += p2 + p3;
            s[nt][0] = p0; s[nt][1] = p1;
            s[nt][2] = p2; s[nt][3] = p3;
            o[nt][0] *= al0; o[nt][1] *= al0;
            o[nt][2] *= al1; o[nt][3] *= al1;
        }
        rs0 += __shfl_xor_sync(0xffffffffu, rs0, 1);
        rs0 += __shfl_xor_sync(0xffffffffu, rs0, 2);
        rs1 += __shfl_xor_sync(0xffffffffu, rs1, 1);
        rs1 += __shfl_xor_sync(0xffffffffu, rs1, 2);
        l0 += rs0; l1 += rs1;

        // ---- O += P @ V ----
#pragma unroll
        for (int kk = 0; kk < 4; kk++) {
            unsigned a0 = h2(s[2 * kk][0],     s[2 * kk][1]);
            unsigned a1 = h2(s[2 * kk][2],     s[2 * kk][3]);
            unsigned a2 = h2(s[2 * kk + 1][0], s[2 * kk + 1][1]);
            unsigned a3 = h2(s[2 * kk + 1][2], s[2 * kk + 1][3]);
            const uint32_t vkb = smb + stB + (uint32_t)(AKH * 2) + vRowB
                               + (uint32_t)(kk * 2048);
#pragma unroll
            for (int ntp = 0; ntp < 4; ntp++) {
                unsigned r0_, r1_, r2_, r3_;
                LDSM_X4T(r0_, r1_, r2_, r3_,
                         vkb + (uint32_t)(((ntp * 2 + hiA) ^ rx) * 16));
                mma_f16(o[2 * ntp],     a0, a1, a2, a3, r0_, r1_);
                mma_f16(o[2 * ntp + 1], a0, a1, a2, a3, r2_, r3_);
            }
        }
        __syncthreads();
    }

    // ---- epilogue ----
    const int b_ = bh >> 4, h = bh & 15;
    const float il0 = 1.f / l0, il1 = 1.f / l1;
    __half* outp = g_attn + ((size_t)b_ * SEQ + qbase) * DMODEL + h * DK;
    const int rl0 = w * 16 + g;
#pragma unroll
    for (int nt = 0; nt < 8; nt++) {
        int dl = nt * 8 + 2 * t;
        *(__half2*)(outp + (size_t)rl0 * DMODEL + dl) =
            __floats2half2_rn(o[nt][0] * il0, o[nt][1] * il0);
        *(__half2*)(outp + (size_t)(rl0 + 8) * DMODEL + dl) =
            __floats2half2_rn(o[nt][2] * il1, o[nt][3] * il1);
    }
}

// ---------- launch ----------
extern "C" void kernel_launch(void* const* d_in, const int* in_sizes, int n_in,
                              void* d_out, int out_size)
{
    const float* q  = (const float*)d_in[0];
    const float* k  = (const float*)d_in[1];
    const float* v  = (const float*)d_in[2];
    const float* wq = (const float*)d_in[4];
    const float* bq = (const float*)d_in[5];
    const float* wk = (const float*)d_in[6];
    const float* bk = (const float*)d_in[7];
    const float* wv = (const float*)d_in[8];
    const float* bv = (const float*)d_in[9];
    const float* wo = (const float*)d_in[10];
    const float* bo = (const float*)d_in[11];

    __half *pq, *pk, *pv, *pa, *phwq, *phwk, *phwv, *phwo;
    cudaGetSymbolAddress((void**)&pq,   g_q);
    cudaGetSymbolAddress((void**)&pk,   g_k);
    cudaGetSymbolAddress((void**)&pv,   g_v);
    cudaGetSymbolAddress((void**)&pa,   g_attn);
    cudaGetSymbolAddress((void**)&phwq, g_hwq);
    cudaGetSymbolAddress((void**)&phwk, g_hwk);
    cudaGetSymbolAddress((void**)&phwv, g_hwv);
    cudaGetSymbolAddress((void**)&phwo, g_hwo);

    cudaFuncSetAttribute(proj_gemm,
                         cudaFuncAttributeMaxDynamicSharedMemorySize,
                         PROJ_SMEM_BYTES);
    cudaFuncSetAttribute(attn_kernel,
                         cudaFuncAttributeMaxDynamicSharedMemorySize,
                         ATTN_SMEM_BYTES);

    cvt_w<<<dim3(512, 4), 256>>>(wq, wk, wv, wo);

    proj_gemm<<<dim3(8, 32, 3), 256, PROJ_SMEM_BYTES>>>(
        q, phwq, bq, pq,
        k, phwk, bk, pk,
        v, phwv, bv, pv, 1, 0);

    attn_kernel<<<dim3(16, 32), 256, ATTN_SMEM_BYTES>>>();

    proj_gemm<<<dim3(8, 32, 1), 256, PROJ_SMEM_BYTES>>>(
        pa, phwo, bo, d_out,
        nullptr, nullptr, nullptr, nullptr,
        nullptr, nullptr, nullptr, nullptr, 0, 1);
}